// round 4
// baseline (speedup 1.0000x reference)
#include <cuda_runtime.h>
#include <cuda_bf16.h>
#include <cstdint>
#include <cstddef>

// ---------------------------------------------------------------- constants
#define DQ   128          // head dim d == projection dim m
#define QN   512          // queries
#define NKEY 131072       // keys
#define KST  512          // stored K per row: [hi(256) | lo(256)]
#define NCHUNK 12         // 12 x 64 logical-K chunks (hh, hl, lh segments)
#define TM 128
#define TN 128
#define KC 64
#define EPSV 1e-8f
// sqrt(pi/2)/128
#define SCALEC 0.009791516697777347f

// ---------------------------------------------------------------- scratch
// Kaug row (512 bf16): [0:128) hi(mse*vn), [128:256) hi(sign*c), [256:384) lo(mse*vn), [384:512) lo(sign*c)
__device__ uint4 g_Kaug4[(size_t)NKEY * KST / 8];       // 128 MB
__device__ uint4 g_Qaug4[(size_t)QN * KST / 8];         // 512 KB
__device__ float g_R[(size_t)NKEY * DQ];                // residuals fp32, 64 MB
__device__ float g_c[NKEY];                             // r_norm*scale*vn
__device__ unsigned long long g_ST2[DQ * 64];           // packed (S[2t][j], S[2t+1][j]) at [j*64+t2]

// ---------------------------------------------------------------- ptx utils
__device__ __forceinline__ uint32_t smem_u32(const void* p) {
    uint32_t a;
    asm("{ .reg .u64 tmp; cvta.to.shared.u64 tmp, %1; cvt.u32.u64 %0, tmp; }" : "=r"(a) : "l"(p));
    return a;
}
__device__ __forceinline__ unsigned long long pack2(float lo, float hi) {
    unsigned long long r;
    asm("mov.b64 %0, {%1, %2};" : "=l"(r) : "r"(__float_as_uint(lo)), "r"(__float_as_uint(hi)));
    return r;
}
__device__ __forceinline__ void unpack2(unsigned long long v, float& lo, float& hi) {
    uint32_t a, b;
    asm("mov.b64 {%0, %1}, %2;" : "=r"(a), "=r"(b) : "l"(v));
    lo = __uint_as_float(a); hi = __uint_as_float(b);
}
__device__ __forceinline__ void fma2(unsigned long long& acc, unsigned long long a, unsigned long long b) {
    asm("fma.rn.f32x2 %0, %1, %2, %3;" : "=l"(acc) : "l"(a), "l"(b), "l"(acc));
}
__device__ __forceinline__ void split_bf16(float v, __nv_bfloat16& h, __nv_bfloat16& l) {
    h = __float2bfloat16(v);
    l = __float2bfloat16(v - __bfloat162float(h));
}

#define SWZ128(off) ((off) ^ (((off) >> 3) & 0x70))

__device__ __forceinline__ void ldsm_x4(uint32_t& r0, uint32_t& r1, uint32_t& r2, uint32_t& r3,
                                        uint32_t addr) {
    asm volatile("ldmatrix.sync.aligned.m8n8.x4.shared.b16 {%0,%1,%2,%3}, [%4];"
        : "=r"(r0), "=r"(r1), "=r"(r2), "=r"(r3) : "r"(addr));
}
__device__ __forceinline__ void mma16816(float* c, const uint32_t* a, const uint32_t* b) {
    asm volatile(
        "mma.sync.aligned.m16n8k16.row.col.f32.bf16.bf16.f32 "
        "{%0,%1,%2,%3}, {%4,%5,%6,%7}, {%8,%9}, {%0,%1,%2,%3};"
        : "+f"(c[0]), "+f"(c[1]), "+f"(c[2]), "+f"(c[3])
        : "r"(a[0]), "r"(a[1]), "r"(a[2]), "r"(a[3]), "r"(b[0]), "r"(b[1]));
}
__device__ __forceinline__ void cp_async16(uint32_t saddr, const void* gptr) {
    asm volatile("cp.async.cg.shared.global [%0], [%1], 16;" :: "r"(saddr), "l"(gptr) : "memory");
}
#define CP_COMMIT() asm volatile("cp.async.commit_group;" ::: "memory")
#define CP_WAIT(n)  asm volatile("cp.async.wait_group %0;" :: "n"(n) : "memory")

// ================================================================ kernel 1
// pack ST2[j*64+t2] = (S[2*t2][j], S[2*t2+1][j])
__global__ void k_prep_S(const float* __restrict__ S) {
    int p = blockIdx.x * 128 + threadIdx.x;     // 8192 total
    int j = p >> 6, t2 = p & 63;
    g_ST2[p] = pack2(S[(2 * t2) * DQ + j], S[(2 * t2 + 1) * DQ + j]);
}

// ================================================================ kernel 2
// per query: qv = [q, q@S^T]; write Qaug = [hi(256) | lo(256)]
__global__ void k_prep_query(const float* __restrict__ query, const float* __restrict__ S) {
    __shared__ float qs[DQ];
    int q = blockIdx.x, t = threadIdx.x;
    qs[t] = query[q * DQ + t];
    __syncthreads();
    float acc = 0.0f;
    const float* srow = S + t * DQ;
    #pragma unroll 8
    for (int j = 0; j < DQ; j++) acc = fmaf(qs[j], srow[j], acc);
    __nv_bfloat16* Qa = (__nv_bfloat16*)g_Qaug4 + (size_t)q * KST;
    __nv_bfloat16 h, l;
    split_bf16(qs[t], h, l);  Qa[t] = h;        Qa[256 + t] = l;
    split_bf16(acc,  h, l);   Qa[128 + t] = h;  Qa[384 + t] = l;
}

// ================================================================ kernel 3
// per key (1 warp): vn, threshold quantize, residual r (to g_R), r_norm,
// Kaug mse hi/lo, g_c
__global__ void k_prep_keysA(const float* __restrict__ keys, const float* __restrict__ cb) {
    int wid = threadIdx.x >> 5, lane = threadIdx.x & 31;
    int n = blockIdx.x * 8 + wid;
    const float* kp = keys + (size_t)n * DQ;

    float kv[4], ss = 0.0f;
    #pragma unroll
    for (int u = 0; u < 4; u++) { kv[u] = kp[u * 32 + lane]; ss = fmaf(kv[u], kv[u], ss); }
    #pragma unroll
    for (int o = 16; o; o >>= 1) ss += __shfl_xor_sync(0xffffffffu, ss, o);
    float vn = sqrtf(ss);
    float dd = vn + EPSV;

    float c0 = cb[0], c1 = cb[1], c2 = cb[2], c3 = cb[3];
    float t01 = 0.5f * (c0 + c1), t12 = 0.5f * (c1 + c2), t23 = 0.5f * (c2 + c3);

    __nv_bfloat16* Ka = (__nv_bfloat16*)g_Kaug4 + (size_t)n * KST;
    float* Rp = g_R + (size_t)n * DQ;
    float rs = 0.0f;
    #pragma unroll
    for (int u = 0; u < 4; u++) {
        float x = kv[u] / dd;
        float xm = c0;
        if (x > t01) xm = c1;
        if (x > t12) xm = c2;
        if (x > t23) xm = c3;
        float r = x - xm;
        rs = fmaf(r, r, rs);
        int j = u * 32 + lane;
        Rp[j] = r;
        __nv_bfloat16 h, l;
        split_bf16(xm * vn, h, l);
        Ka[j] = h; Ka[256 + j] = l;
    }
    #pragma unroll
    for (int o = 16; o; o >>= 1) rs += __shfl_xor_sync(0xffffffffu, rs, o);
    if (lane == 0) g_c[n] = sqrtf(rs) * SCALEC * vn;
}

// ================================================================ kernel 4
// P = R @ S^T in fp32 (f32x2 packed), signs -> Kaug sign hi/lo
// CTA: 64 keys x 128 t, 256 threads, smem: Rs[64][129] f32 + ST2s[8192] ull
#define PB_SMEM (64 * 129 * 4 + 8192 * 8)
__global__ void __launch_bounds__(256, 2) k_prep_keysB() {
    extern __shared__ char sm[];
    float* Rs = (float*)sm;
    unsigned long long* ST2s = (unsigned long long*)(sm + 64 * 129 * 4);
    int tid = threadIdx.x;
    int key0 = blockIdx.x * 64;

    for (int i = tid; i < 8192; i += 256) ST2s[i] = g_ST2[i];
    for (int i = tid; i < 64 * 128; i += 256) {
        int row = i >> 7, j = i & 127;
        Rs[row * 129 + j] = g_R[(size_t)(key0 + row) * DQ + j];
    }
    __syncthreads();

    int tx = tid & 15, ty = tid >> 4;
    unsigned long long acc[4][4];
    #pragma unroll
    for (int i = 0; i < 4; i++)
        #pragma unroll
        for (int u = 0; u < 4; u++) acc[i][u] = 0ULL;

    #pragma unroll 4
    for (int j = 0; j < DQ; j++) {
        unsigned long long b[4];
        #pragma unroll
        for (int u = 0; u < 4; u++) b[u] = ST2s[j * 64 + tx + 16 * u];
        #pragma unroll
        for (int i = 0; i < 4; i++) {
            float a = Rs[(ty * 4 + i) * 129 + j];
            unsigned long long a2 = pack2(a, a);
            #pragma unroll
            for (int u = 0; u < 4; u++) fma2(acc[i][u], a2, b[u]);
        }
    }

    #pragma unroll
    for (int i = 0; i < 4; i++) {
        int n = key0 + ty * 4 + i;
        float cn = g_c[n];
        __nv_bfloat16 ch, cl;
        split_bf16(cn, ch, cl);
        __nv_bfloat162* Hi = (__nv_bfloat162*)((__nv_bfloat16*)g_Kaug4 + (size_t)n * KST + 128);
        __nv_bfloat162* Lo = (__nv_bfloat162*)((__nv_bfloat16*)g_Kaug4 + (size_t)n * KST + 384);
        #pragma unroll
        for (int u = 0; u < 4; u++) {
            int t2 = tx + 16 * u;
            float p0, p1;
            unpack2(acc[i][u], p0, p1);
            __nv_bfloat162 hv, lv;
            hv.x = (p0 >= 0.0f) ? ch : __hneg(ch);
            hv.y = (p1 >= 0.0f) ? ch : __hneg(ch);
            lv.x = (p0 >= 0.0f) ? cl : __hneg(cl);
            lv.y = (p1 >= 0.0f) ? cl : __hneg(cl);
            Hi[t2] = hv;
            Lo[t2] = lv;
        }
    }
}

// ================================================================ kernel 5
// out[512, 131072] = Qaug @ Kaug^T via mma.sync m16n8k16 bf16 (HMMA),
// exact hi/lo split as 12 x 64-col chunks. CTA 128(M) x 128(N), 256 thr,
// 8 warps = 2(M) x 4(N), warp tile 64x32, double-buffered cp.async.
#define GE_STAGE 32768             // A 16KB + B 16KB
#define GE_SMEM  (2 * GE_STAGE)
__global__ void __launch_bounds__(256) k_gemm(float* __restrict__ out) {
    extern __shared__ char sm[];
    uint32_t sb = smem_u32(sm);
    int tid = threadIdx.x, wid = tid >> 5, lane = tid & 31;
    int nstrip = blockIdx.x >> 2;       // N-major: 4 M-tiles adjacent share B via L2
    int mtile  = blockIdx.x & 3;
    int key0 = nstrip * TN;

    int wm = wid >> 2, wn = wid & 3;    // warp tile: rows wm*64.., cols wn*32..

    // ldmatrix per-lane address components
    int rowA = (lane & 7) + ((lane >> 3) & 1) * 8;   // A frags
    int byteA = (lane >> 4) * 16;
    int rowB = (lane & 7) + (lane >> 4) * 8;         // B frags
    int byteB = ((lane >> 3) & 1) * 16;

    // loader: 2048 uint4 per stage (A first 1024, B next 1024), 8 per thread
    int lrow = (tid * 8 & 1023) >> 3;   // = tid*8/8 % 128
    // each thread loads u=0..7 of one row per half; simpler: idx-based below

    float acc[4][4][4];
    #pragma unroll
    for (int i = 0; i < 4; i++)
        #pragma unroll
        for (int j = 0; j < 4; j++)
            #pragma unroll
            for (int r = 0; r < 4; r++) acc[i][j][r] = 0.0f;

    const uint4* QA = g_Qaug4;
    const uint4* KA = g_Kaug4;

    // ---- chunk prefetch lambda (manual) ----
    // chunk c: seg = c>>2 (0:hh 1:hl 2:lh), s=(c&3)*64
    // acol = (seg==2?256:0)+s (A, query cols), bcol = (seg==1?256:0)+s (B)
    #define PREFETCH(c, buf) do { \
        int seg_ = (c) >> 2, s_ = ((c) & 3) * 64; \
        int acol8_ = ((seg_ == 2 ? 256 : 0) + s_) >> 3; \
        int bcol8_ = ((seg_ == 1 ? 256 : 0) + s_) >> 3; \
        uint32_t base_ = sb + (buf) * GE_STAGE; \
        _Pragma("unroll") \
        for (int it_ = 0; it_ < 8; it_++) { \
            int idx_ = tid + it_ * 256; \
            int half_ = idx_ >> 10; \
            int w_ = idx_ & 1023; \
            int row_ = w_ >> 3, u_ = w_ & 7; \
            const uint4* gp_; \
            if (half_ == 0) gp_ = QA + (size_t)(mtile * TM + row_) * 64 + acol8_ + u_; \
            else            gp_ = KA + (size_t)(key0 + row_) * 64 + bcol8_ + u_; \
            uint32_t off_ = ((uint32_t)(row_ >> 3) << 10) | ((uint32_t)(row_ & 7) << 7) | ((uint32_t)u_ << 4); \
            off_ = SWZ128(off_); \
            cp_async16(base_ + half_ * 16384 + off_, gp_); \
        } \
        CP_COMMIT(); \
    } while (0)

    PREFETCH(0, 0);

    for (int c = 0; c < NCHUNK; c++) {
        if (c + 1 < NCHUNK) { PREFETCH(c + 1, (c + 1) & 1); CP_WAIT(1); }
        else                { CP_WAIT(0); }
        __syncthreads();

        uint32_t aBase = sb + (c & 1) * GE_STAGE;
        uint32_t bBase = aBase + 16384;

        #pragma unroll
        for (int k16 = 0; k16 < 4; k16++) {
            int kb = k16 * 32;
            uint32_t af[4][4], bf[2][4];
            #pragma unroll
            for (int im = 0; im < 4; im++) {
                int r = wm * 64 + im * 16 + rowA;
                uint32_t off = ((uint32_t)(r >> 3) << 10) | ((uint32_t)(r & 7) << 7) |
                               (uint32_t)(kb + byteA);
                ldsm_x4(af[im][0], af[im][1], af[im][2], af[im][3], aBase + SWZ128(off));
            }
            #pragma unroll
            for (int pr = 0; pr < 2; pr++) {
                int r = wn * 32 + pr * 16 + rowB;
                uint32_t off = ((uint32_t)(r >> 3) << 10) | ((uint32_t)(r & 7) << 7) |
                               (uint32_t)(kb + byteB);
                ldsm_x4(bf[pr][0], bf[pr][1], bf[pr][2], bf[pr][3], bBase + SWZ128(off));
            }
            #pragma unroll
            for (int im = 0; im < 4; im++) {
                #pragma unroll
                for (int in = 0; in < 4; in++) {
                    // n-subtile in: pair pr = in>>1, frag = (bf[pr][0..1] or bf[pr][2..3])
                    mma16816(acc[im][in], af[im], &bf[in >> 1][(in & 1) * 2]);
                }
            }
        }
        __syncthreads();
    }

    // ---- epilogue: direct fp32 stores ----
    int tq = lane >> 2, tn2 = (lane & 3) * 2;
    #pragma unroll
    for (int im = 0; im < 4; im++) {
        #pragma unroll
        for (int in = 0; in < 4; in++) {
            int m = mtile * TM + wm * 64 + im * 16 + tq;
            int n = key0 + wn * 32 + in * 8 + tn2;
            float2 v0 = make_float2(acc[im][in][0], acc[im][in][1]);
            float2 v1 = make_float2(acc[im][in][2], acc[im][in][3]);
            *(float2*)(out + (size_t)m * NKEY + n) = v0;
            *(float2*)(out + (size_t)(m + 8) * NKEY + n) = v1;
        }
    }
    #undef PREFETCH
}

// ================================================================ launch
extern "C" void kernel_launch(void* const* d_in, const int* in_sizes, int n_in,
                              void* d_out, int out_size) {
    const float* query = (const float*)d_in[0];
    const float* keys  = (const float*)d_in[1];
    const float* cb    = (const float*)d_in[2];
    const float* S     = (const float*)d_in[3];
    float* out = (float*)d_out;

    static bool attr_done = false;
    if (!attr_done) {
        cudaFuncSetAttribute(k_prep_keysB, cudaFuncAttributeMaxDynamicSharedMemorySize, PB_SMEM);
        cudaFuncSetAttribute(k_gemm, cudaFuncAttributeMaxDynamicSharedMemorySize, GE_SMEM);
        attr_done = true;
    }

    k_prep_S<<<64, 128>>>(S);
    k_prep_query<<<QN, 128>>>(query, S);
    k_prep_keysA<<<NKEY / 8, 256>>>(keys, cb);
    k_prep_keysB<<<NKEY / 64, 256, PB_SMEM>>>();
    k_gemm<<<(NKEY / TN) * (QN / TM), 256, GE_SMEM>>>(out);
}

// round 5
// speedup vs baseline: 1.6847x; 1.6847x over previous
#include <cuda_runtime.h>
#include <cuda_bf16.h>
#include <cuda_fp16.h>
#include <cstdint>
#include <cstddef>

// ---------------------------------------------------------------- constants
#define DQ   128          // head dim d == projection dim m
#define QN   512          // queries
#define NKEY 131072       // keys
#define KH   256          // fp16 halves per augmented row: [0:128) mse*vn, [128:256) sign*c
#define NCHUNK 4          // 4 x 64-col K chunks
#define TM 128
#define TN 128
#define EPSV 1e-8f
// sqrt(pi/2)/128
#define SCALEC 0.009791516697777347f

// ---------------------------------------------------------------- scratch
__device__ uint4 g_Kaug4[(size_t)NKEY * KH / 8];        // 64 MB fp16
__device__ uint4 g_Qaug4[(size_t)QN * KH / 8];          // 256 KB fp16
__device__ unsigned long long g_ST2[DQ * 64];           // packed (S[2t][j], S[2t+1][j]) at [j*64+t2]

// ---------------------------------------------------------------- ptx utils
__device__ __forceinline__ uint32_t smem_u32(const void* p) {
    uint32_t a;
    asm("{ .reg .u64 tmp; cvta.to.shared.u64 tmp, %1; cvt.u32.u64 %0, tmp; }" : "=r"(a) : "l"(p));
    return a;
}
__device__ __forceinline__ unsigned long long pack2(float lo, float hi) {
    unsigned long long r;
    asm("mov.b64 %0, {%1, %2};" : "=l"(r) : "r"(__float_as_uint(lo)), "r"(__float_as_uint(hi)));
    return r;
}
__device__ __forceinline__ void unpack2(unsigned long long v, float& lo, float& hi) {
    uint32_t a, b;
    asm("mov.b64 {%0, %1}, %2;" : "=r"(a), "=r"(b) : "l"(v));
    lo = __uint_as_float(a); hi = __uint_as_float(b);
}
__device__ __forceinline__ void fma2(unsigned long long& acc, unsigned long long a, unsigned long long b) {
    asm("fma.rn.f32x2 %0, %1, %2, %3;" : "=l"(acc) : "l"(a), "l"(b), "l"(acc));
}
__device__ __forceinline__ uint32_t h2pack(float a, float b) {
    __half2 h = __floats2half2_rn(a, b);   // a -> low half (memory-first)
    return *(uint32_t*)&h;
}

#define SWZ128(off) ((off) ^ (((off) >> 3) & 0x70))

__device__ __forceinline__ void ldsm_x4(uint32_t& r0, uint32_t& r1, uint32_t& r2, uint32_t& r3,
                                        uint32_t addr) {
    asm volatile("ldmatrix.sync.aligned.m8n8.x4.shared.b16 {%0,%1,%2,%3}, [%4];"
        : "=r"(r0), "=r"(r1), "=r"(r2), "=r"(r3) : "r"(addr));
}
__device__ __forceinline__ void mma16816(float* c, const uint32_t* a, const uint32_t* b) {
    asm volatile(
        "mma.sync.aligned.m16n8k16.row.col.f32.f16.f16.f32 "
        "{%0,%1,%2,%3}, {%4,%5,%6,%7}, {%8,%9}, {%0,%1,%2,%3};"
        : "+f"(c[0]), "+f"(c[1]), "+f"(c[2]), "+f"(c[3])
        : "r"(a[0]), "r"(a[1]), "r"(a[2]), "r"(a[3]), "r"(b[0]), "r"(b[1]));
}
__device__ __forceinline__ void cp_async16(uint32_t saddr, const void* gptr) {
    asm volatile("cp.async.cg.shared.global [%0], [%1], 16;" :: "r"(saddr), "l"(gptr) : "memory");
}
#define CP_COMMIT() asm volatile("cp.async.commit_group;" ::: "memory")
#define CP_WAIT(n)  asm volatile("cp.async.wait_group %0;" :: "n"(n) : "memory")

// ================================================================ kernel 1
// pack ST2[j*64+t2] = (S[2*t2][j], S[2*t2+1][j]),  t2 = 4*tx+u layout
__global__ void k_prep_S(const float* __restrict__ S) {
    int p = blockIdx.x * 128 + threadIdx.x;     // 8192 total
    int j = p >> 6, t2 = p & 63;
    g_ST2[p] = pack2(S[(2 * t2) * DQ + j], S[(2 * t2 + 1) * DQ + j]);
}

// ================================================================ kernel 2
// per query: Qaug(fp16) = [q (128) | q@S^T (128)]
__global__ void k_prep_query(const float* __restrict__ query, const float* __restrict__ S) {
    __shared__ float qs[DQ];
    int q = blockIdx.x, t = threadIdx.x;
    qs[t] = query[q * DQ + t];
    __syncthreads();
    float acc = 0.0f;
    const float* srow = S + t * DQ;
    #pragma unroll 8
    for (int j = 0; j < DQ; j++) acc = fmaf(qs[j], srow[j], acc);
    __half* Qa = (__half*)g_Qaug4 + (size_t)q * KH;
    Qa[t]       = __float2half_rn(qs[t]);
    Qa[128 + t] = __float2half_rn(acc);
}

// ================================================================ kernel 3
// FUSED key prep. CTA = 64 keys, 256 threads.
//  phase 1: load keys, norms, 4-level quantize, residual -> smem, mse fp16 -> Kaug
//  phase 2: P = R @ S^T in fp32 f32x2; signs * c (fp16) -> Kaug
#define RS_LD 132
#define PF_SMEM (64 * RS_LD * 4 + 8192 * 8 + 64 * 4)
__global__ void __launch_bounds__(256, 2) k_prep_keys(const float* __restrict__ keys,
                                                      const float* __restrict__ cb) {
    extern __shared__ char sm[];
    float* Rs = (float*)sm;                                    // 64 x 132 fp32
    unsigned long long* ST2s = (unsigned long long*)(sm + 64 * RS_LD * 4);  // 64 KB
    float* cs = (float*)(sm + 64 * RS_LD * 4 + 8192 * 8);      // 64 floats
    int tid = threadIdx.x;
    int key0 = blockIdx.x * 64;

    // stage S into smem
    for (int i = tid; i < 8192; i += 256) ST2s[i] = g_ST2[i];

    // ---- phase 1: thread t handles row = t>>2, quarter = t&3 (32 coords)
    int row = tid >> 2, qtr = tid & 3;
    int n = key0 + row;
    const float4* kp = (const float4*)(keys + (size_t)n * DQ + qtr * 32);
    float4 kf[8];
    float ss = 0.0f;
    #pragma unroll
    for (int g = 0; g < 8; g++) {
        kf[g] = kp[g];
        ss = fmaf(kf[g].x, kf[g].x, ss);
        ss = fmaf(kf[g].y, kf[g].y, ss);
        ss = fmaf(kf[g].z, kf[g].z, ss);
        ss = fmaf(kf[g].w, kf[g].w, ss);
    }
    ss += __shfl_xor_sync(0xffffffffu, ss, 1);
    ss += __shfl_xor_sync(0xffffffffu, ss, 2);
    float vn = sqrtf(ss);
    float inv = 1.0f / (vn + EPSV);

    float c0 = cb[0], c1 = cb[1], c2 = cb[2], c3 = cb[3];
    float t01 = 0.5f * (c0 + c1), t12 = 0.5f * (c1 + c2), t23 = 0.5f * (c2 + c3);

    float rs = 0.0f;
    uint32_t hw[16];                                    // 32 mse halves
    float* rrow = Rs + row * RS_LD + qtr * 32;
    #pragma unroll
    for (int g = 0; g < 8; g++) {
        float xv[4] = {kf[g].x, kf[g].y, kf[g].z, kf[g].w};
        float rv[4];
        float mv[4];
        #pragma unroll
        for (int e = 0; e < 4; e++) {
            float x = xv[e] * inv;
            float xm = c0;
            if (x > t01) xm = c1;
            if (x > t12) xm = c2;
            if (x > t23) xm = c3;
            float r = x - xm;
            rs = fmaf(r, r, rs);
            rv[e] = r;
            mv[e] = xm * vn;
        }
        *(float4*)(rrow + g * 4) = make_float4(rv[0], rv[1], rv[2], rv[3]);
        hw[g * 2 + 0] = h2pack(mv[0], mv[1]);
        hw[g * 2 + 1] = h2pack(mv[2], mv[3]);
    }
    // mse fp16 -> Kaug[n][qtr*32 .. +31]  (uint4 idx qtr*4 + w)
    {
        uint4* Ka = g_Kaug4 + (size_t)n * (KH / 8) + qtr * 4;
        #pragma unroll
        for (int w = 0; w < 4; w++)
            Ka[w] = make_uint4(hw[w * 4 + 0], hw[w * 4 + 1], hw[w * 4 + 2], hw[w * 4 + 3]);
    }
    rs += __shfl_xor_sync(0xffffffffu, rs, 1);
    rs += __shfl_xor_sync(0xffffffffu, rs, 2);
    if (qtr == 0) cs[row] = sqrtf(rs) * SCALEC * vn;
    __syncthreads();

    // ---- phase 2: tx = tid&15 (t2 = 4*tx+u), ty = tid>>4 (rows ty*4+i)
    int tx = tid & 15, ty = tid >> 4;
    unsigned long long acc[4][4];
    #pragma unroll
    for (int i = 0; i < 4; i++)
        #pragma unroll
        for (int u = 0; u < 4; u++) acc[i][u] = 0ULL;

    const float4* arow[4];
    #pragma unroll
    for (int i = 0; i < 4; i++) arow[i] = (const float4*)(Rs + (ty * 4 + i) * RS_LD);

    #pragma unroll 2
    for (int j4 = 0; j4 < 32; j4++) {
        float4 a4[4];
        #pragma unroll
        for (int i = 0; i < 4; i++) a4[i] = arow[i][j4];
        #pragma unroll
        for (int jj = 0; jj < 4; jj++) {
            int j = j4 * 4 + jj;
            const ulonglong2* bp = (const ulonglong2*)(ST2s + j * 64 + tx * 4);
            ulonglong2 b01 = bp[0], b23 = bp[1];
            #pragma unroll
            for (int i = 0; i < 4; i++) {
                float av = (jj == 0) ? a4[i].x : (jj == 1) ? a4[i].y : (jj == 2) ? a4[i].z : a4[i].w;
                unsigned long long a2 = pack2(av, av);
                fma2(acc[i][0], a2, b01.x);
                fma2(acc[i][1], a2, b01.y);
                fma2(acc[i][2], a2, b23.x);
                fma2(acc[i][3], a2, b23.y);
            }
        }
    }

    #pragma unroll
    for (int i = 0; i < 4; i++) {
        int nn = key0 + ty * 4 + i;
        float c = cs[ty * 4 + i];
        uint32_t w[4];
        #pragma unroll
        for (int u = 0; u < 4; u++) {
            float p0, p1;
            unpack2(acc[i][u], p0, p1);
            w[u] = h2pack(p0 >= 0.0f ? c : -c, p1 >= 0.0f ? c : -c);
        }
        // sign halves at [128 + 8*tx .. +7] -> uint4 idx 16 + tx
        g_Kaug4[(size_t)nn * (KH / 8) + 16 + tx] = make_uint4(w[0], w[1], w[2], w[3]);
    }
}

// ================================================================ kernel 4
// out[512, 131072] = Qaug @ Kaug^T via mma.sync m16n8k16 fp16->fp32, K=256.
// CTA 128(M) x 128(N), 256 thr, 8 warps = 2(M) x 4(N), warp tile 64x32,
// double-buffered cp.async.
#define GE_STAGE 32768             // A 16KB + B 16KB
#define GE_SMEM  (2 * GE_STAGE)
__global__ void __launch_bounds__(256) k_gemm(float* __restrict__ out) {
    extern __shared__ char sm[];
    uint32_t sb = smem_u32(sm);
    int tid = threadIdx.x, wid = tid >> 5, lane = tid & 31;
    int nstrip = blockIdx.x >> 2;       // N-major: 4 M-tiles adjacent share B via L2
    int mtile  = blockIdx.x & 3;
    int key0 = nstrip * TN;

    int wm = wid >> 2, wn = wid & 3;    // warp tile: rows wm*64.., cols wn*32..

    int rowA = (lane & 7) + ((lane >> 3) & 1) * 8;   // A frags
    int byteA = (lane >> 4) * 16;
    int rowB = (lane & 7) + (lane >> 4) * 8;         // B frags
    int byteB = ((lane >> 3) & 1) * 16;

    float acc[4][4][4];
    #pragma unroll
    for (int i = 0; i < 4; i++)
        #pragma unroll
        for (int j = 0; j < 4; j++)
            #pragma unroll
            for (int r = 0; r < 4; r++) acc[i][j][r] = 0.0f;

    const uint4* QA = g_Qaug4;
    const uint4* KA = g_Kaug4;

    // chunk c covers fp16 cols [c*64, c*64+64) = uint4 [c*8, c*8+8) of the 32/row
    #define PREFETCH(c, buf) do { \
        int col8_ = (c) * 8; \
        uint32_t base_ = sb + (buf) * GE_STAGE; \
        _Pragma("unroll") \
        for (int it_ = 0; it_ < 8; it_++) { \
            int idx_ = tid + it_ * 256; \
            int half_ = idx_ >> 10; \
            int w_ = idx_ & 1023; \
            int row_ = w_ >> 3, u_ = w_ & 7; \
            const uint4* gp_; \
            if (half_ == 0) gp_ = QA + (size_t)(mtile * TM + row_) * 32 + col8_ + u_; \
            else            gp_ = KA + (size_t)(key0 + row_) * 32 + col8_ + u_; \
            uint32_t off_ = ((uint32_t)(row_ >> 3) << 10) | ((uint32_t)(row_ & 7) << 7) | ((uint32_t)u_ << 4); \
            off_ = SWZ128(off_); \
            cp_async16(base_ + half_ * 16384 + off_, gp_); \
        } \
        CP_COMMIT(); \
    } while (0)

    PREFETCH(0, 0);

    for (int c = 0; c < NCHUNK; c++) {
        if (c + 1 < NCHUNK) { PREFETCH(c + 1, (c + 1) & 1); CP_WAIT(1); }
        else                { CP_WAIT(0); }
        __syncthreads();

        uint32_t aBase = sb + (c & 1) * GE_STAGE;
        uint32_t bBase = aBase + 16384;

        #pragma unroll
        for (int k16 = 0; k16 < 4; k16++) {
            int kb = k16 * 32;
            uint32_t af[4][4], bf[2][4];
            #pragma unroll
            for (int im = 0; im < 4; im++) {
                int r = wm * 64 + im * 16 + rowA;
                uint32_t off = ((uint32_t)(r >> 3) << 10) | ((uint32_t)(r & 7) << 7) |
                               (uint32_t)(kb + byteA);
                ldsm_x4(af[im][0], af[im][1], af[im][2], af[im][3], aBase + SWZ128(off));
            }
            #pragma unroll
            for (int pr = 0; pr < 2; pr++) {
                int r = wn * 32 + pr * 16 + rowB;
                uint32_t off = ((uint32_t)(r >> 3) << 10) | ((uint32_t)(r & 7) << 7) |
                               (uint32_t)(kb + byteB);
                ldsm_x4(bf[pr][0], bf[pr][1], bf[pr][2], bf[pr][3], bBase + SWZ128(off));
            }
            #pragma unroll
            for (int im = 0; im < 4; im++) {
                #pragma unroll
                for (int in = 0; in < 4; in++) {
                    mma16816(acc[im][in], af[im], &bf[in >> 1][(in & 1) * 2]);
                }
            }
        }
        __syncthreads();
    }

    // ---- epilogue: direct fp32 stores ----
    int tq = lane >> 2, tn2 = (lane & 3) * 2;
    #pragma unroll
    for (int im = 0; im < 4; im++) {
        #pragma unroll
        for (int in = 0; in < 4; in++) {
            int m = mtile * TM + wm * 64 + im * 16 + tq;
            int n = key0 + wn * 32 + in * 8 + tn2;
            float2 v0 = make_float2(acc[im][in][0], acc[im][in][1]);
            float2 v1 = make_float2(acc[im][in][2], acc[im][in][3]);
            *(float2*)(out + (size_t)m * NKEY + n) = v0;
            *(float2*)(out + (size_t)(m + 8) * NKEY + n) = v1;
        }
    }
    #undef PREFETCH
}

// ================================================================ launch
extern "C" void kernel_launch(void* const* d_in, const int* in_sizes, int n_in,
                              void* d_out, int out_size) {
    const float* query = (const float*)d_in[0];
    const float* keys  = (const float*)d_in[1];
    const float* cb    = (const float*)d_in[2];
    const float* S     = (const float*)d_in[3];
    float* out = (float*)d_out;

    static bool attr_done = false;
    if (!attr_done) {
        cudaFuncSetAttribute(k_prep_keys, cudaFuncAttributeMaxDynamicSharedMemorySize, PF_SMEM);
        cudaFuncSetAttribute(k_gemm, cudaFuncAttributeMaxDynamicSharedMemorySize, GE_SMEM);
        attr_done = true;
    }

    k_prep_S<<<64, 128>>>(S);
    k_prep_query<<<QN, 128>>>(query, S);
    k_prep_keys<<<NKEY / 64, 256, PF_SMEM>>>(keys, cb);
    k_gemm<<<(NKEY / TN) * (QN / TM), 256, GE_SMEM>>>(out);
}